// round 14
// baseline (speedup 1.0000x reference)
#include <cuda_runtime.h>
#include <cuda_bf16.h>
#include <cuda_fp16.h>
#include <math.h>
#include <stdint.h>

#define NN 50000
#define EE 600000
#define DD 128
#define GNH 5000
#define GNE 60000
#define NG 10
#define EPS_NORM 1e-5f
#define EPS_RED  1e-6f

#define MT 64
#define NODE_TILES ((NN + MT - 1) / MT)   // 782
#define EDGE_TILES (EE / MT)              // 9375 (exact)

// ---- GEMM smem layout (f16 2-pass, shared by node and edge kernels) ----
#define EW_HI 17408
#define EW_LO 52224
#define E_SMEM 87040

// ---------------- scratch (device globals; no allocation allowed) ----------
__device__ float g_Ah[NN * DD];
__device__ __half g_DB[NN * 256];    // src-indexed f16: [node][0:128)=Dh, [128:256)=Bh
__device__ __half g_EhH[NN * DD];    // dst-indexed f16 Eh
__device__ __half g_EW[(size_t)EE * DD];  // f16 staged e_new*snorm
__device__ float g_num[NN * DD];
__device__ float g_den[NN * DD];
__device__ float g_sum[2 * NG * DD];
__device__ float g_sq[2 * NG * DD];
__device__ __half g_Wh_hi[5 * DD * DD];   // transposed [l][n][k], f16 hi
__device__ __half g_Wh_lo[5 * DD * DD];   // f16 lo (residual)

// ---------------- helpers ----------------------------------------------------
__device__ __forceinline__ uint32_t smem_u32(const void* p) {
    uint32_t a;
    asm("{ .reg .u64 t; cvta.to.shared.u64 t, %1; cvt.u32.u64 %0, t; }" : "=r"(a) : "l"(p));
    return a;
}
__device__ __forceinline__ void ldsm4(uint32_t a[4], uint32_t addr) {
    asm volatile("ldmatrix.sync.aligned.m8n8.x4.shared.b16 {%0,%1,%2,%3}, [%4];"
                 : "=r"(a[0]), "=r"(a[1]), "=r"(a[2]), "=r"(a[3]) : "r"(addr));
}
__device__ __forceinline__ void mma16816h(float c[4], const uint32_t a[4],
                                          uint32_t b0, uint32_t b1) {
    asm volatile("mma.sync.aligned.m16n8k16.row.col.f32.f16.f16.f32 "
                 "{%0,%1,%2,%3}, {%4,%5,%6,%7}, {%8,%9}, {%0,%1,%2,%3};"
                 : "+f"(c[0]), "+f"(c[1]), "+f"(c[2]), "+f"(c[3])
                 : "r"(a[0]), "r"(a[1]), "r"(a[2]), "r"(a[3]), "r"(b0), "r"(b1));
}
__device__ __forceinline__ void redv4(float* p, float4 v) {
    asm volatile("red.global.add.v4.f32 [%0], {%1,%2,%3,%4};"
                 :: "l"(p), "f"(v.x), "f"(v.y), "f"(v.z), "f"(v.w) : "memory");
}
__device__ __forceinline__ void prefetchL2(const void* p) {
    asm volatile("prefetch.global.L2 [%0];" :: "l"(p));
}
// sigmoid via single-MUFU tanh: sig(x) = 0.5*tanh(x/2) + 0.5
__device__ __forceinline__ float sigt(float x) {
    float t;
    asm("tanh.approx.f32 %0, %1;" : "=f"(t) : "f"(x * 0.5f));
    return fmaf(t, 0.5f, 0.5f);
}

// transpose + f16 hi/lo split: Wh[l][n][k] = f16(W[l][k][n]) + residual.
// Also zeros the tiny g_sum/g_sq stat accumulators (runs before both GEMMs).
__global__ void splitW_kernel(const float* __restrict__ W) {
    int i = blockIdx.x * blockDim.x + threadIdx.x;
    if (i < 2 * NG * DD) { g_sum[i] = 0.f; g_sq[i] = 0.f; }
    if (i >= 5 * DD * DD) return;
    int l = i >> 14, j = i & 16383, n = j >> 7, k = j & 127;
    float v = W[(l << 14) + (k << 7) + n];
    __half hh = __float2half_rn(v);
    g_Wh_hi[i] = hh;
    g_Wh_lo[i] = __float2half_rn(v - __half2float(hh));
}

// ---------------- W loader (once per CTA) -------------------------------------
__device__ __forceinline__ void load_W_generic(char* sm,
                                               const uint32_t* __restrict__ WH,
                                               const uint32_t* __restrict__ WL) {
    for (int u = threadIdx.x; u < 128 * 64; u += 256) {
        int r = u >> 6, kk = u & 63;
        *(uint32_t*)(sm + EW_HI + r * 272 + kk * 4) = WH[u];
        *(uint32_t*)(sm + EW_LO + r * 272 + kk * 4) = WL[u];
    }
}

// ---------------- A-tile prefetch (f32 -> regs) --------------------------------
template <bool STREAM>
__device__ __forceinline__ void prefetch_tile(const float* __restrict__ X,
                                              long tile, int M, float2 pf[16]) {
    const float2* X2 = (const float2*)X;
    const int t = threadIdx.x;
#pragma unroll
    for (int j = 0; j < 16; j++) {
        int u = t + j * 256;
        int r = u >> 6, kk = u & 63;
        long grow = tile * MT + r;
        if (grow < M) pf[j] = STREAM ? __ldcs(&X2[grow * 64 + kk]) : X2[grow * 64 + kk];
        else          pf[j] = make_float2(0.f, 0.f);
    }
}
// f16 commit (A at smem offset 0)
__device__ __forceinline__ void commit_tile_f16(char* sm, const float2 pf[16]) {
    const int t = threadIdx.x;
#pragma unroll
    for (int j = 0; j < 16; j++) {
        int u = t + j * 256;
        int r = u >> 6, kk = u & 63;
        *(__half2*)(sm + r * 272 + kk * 4) = __floats2half2_rn(pf[j].x, pf[j].y);
    }
}

// ---------------- warp-mma: f16 2-pass, 64x128 tile ----------------------------
__device__ __forceinline__ void mma_compute_f16(uint32_t smb, float c[2][4][4]) {
    const int lane = threadIdx.x & 31;
    const int w = threadIdx.x >> 5;
    const int m0 = (w & 1) * 32, n0 = (w >> 1) * 32;
#pragma unroll
    for (int m = 0; m < 2; m++)
#pragma unroll
        for (int n = 0; n < 4; n++)
#pragma unroll
            for (int i = 0; i < 4; i++) c[m][n][i] = 0.f;

    const uint32_t aBase = smb + (m0 + (lane & 15)) * 272 + (lane >> 4) * 16;
    const uint32_t bBase = smb + EW_HI +
        (n0 + (lane & 7) + ((lane >> 4) & 1) * 8) * 272 + ((lane >> 3) & 1) * 16;

#pragma unroll
    for (int k = 0; k < 8; k++) {
        uint32_t aH0[4], aH1[4];
        ldsm4(aH0, aBase + k * 32);
        ldsm4(aH1, aBase + 16 * 272 + k * 32);
#pragma unroll
        for (int np = 0; np < 2; np++) {
            uint32_t bH[4], bL[4];
            ldsm4(bH, bBase + np * 16 * 272 + k * 32);
            ldsm4(bL, bBase + (EW_LO - EW_HI) + np * 16 * 272 + k * 32);
#pragma unroll
            for (int nn = 0; nn < 2; nn++) {
                const int nc = np * 2 + nn;
                mma16816h(c[0][nc], aH0, bH[nn * 2], bH[nn * 2 + 1]);
                mma16816h(c[1][nc], aH1, bH[nn * 2], bH[nn * 2 + 1]);
                mma16816h(c[0][nc], aH0, bL[nn * 2], bL[nn * 2 + 1]);
                mma16816h(c[1][nc], aH1, bL[nn * 2], bL[nn * 2 + 1]);
            }
        }
    }
}

// ---------------- node GEMMs: persistent tiles, layer = blockIdx.y -----------
// y=0 -> Ah f32 (stride 128) + zeroes g_num/g_den rows; y=1 -> Bh f16 (g_DB+128);
// y=2 -> Dh f16 (g_DB); y=3 -> Eh f16 (g_EhH)
__global__ void __launch_bounds__(256, 2) node_gemm(const float* __restrict__ h,
                                                    const float* __restrict__ b) {
    extern __shared__ __align__(16) char sm[];
    const int lmap[4] = {0, 1, 3, 4};
    const int l = lmap[blockIdx.y];
    __half* outh;
    int ostride = 256;
    if (blockIdx.y == 1)      outh = g_DB + 128;
    else if (blockIdx.y == 2) outh = g_DB;
    else                      { outh = g_EhH; ostride = 128; }
    load_W_generic(sm, (const uint32_t*)(g_Wh_hi + l * DD * DD),
                   (const uint32_t*)(g_Wh_lo + l * DD * DD));

    const uint32_t smb = smem_u32(sm);
    const float* bias = b + l * DD;
    const int lane = threadIdx.x & 31, w = threadIdx.x >> 5;
    const int m0 = (w & 1) * 32, n0 = (w >> 1) * 32;
    const int tig = lane & 3, gg = lane >> 2;
    const float2 z2 = make_float2(0.f, 0.f);

    float2 pf[16];
    long tile = blockIdx.x;
    if (tile < NODE_TILES) prefetch_tile<false>(h, tile, NN, pf);
    for (; tile < NODE_TILES; tile += gridDim.x) {
        commit_tile_f16(sm, pf);
        __syncthreads();
        long nt = tile + gridDim.x;
        if (nt < NODE_TILES) prefetch_tile<false>(h, nt, NN, pf);

        float c[2][4][4];
        mma_compute_f16(smb, c);

#pragma unroll
        for (int m = 0; m < 2; m++) {
            long r0 = tile * MT + m0 + m * 16 + gg;
#pragma unroll
            for (int n = 0; n < 4; n++) {
                int col = n0 + n * 8 + tig * 2;
                float2 bv = *(const float2*)(bias + col);
                if (blockIdx.y == 0) {
                    if (r0 < NN) {
                        *(float2*)(g_Ah + r0 * DD + col) =
                            make_float2(c[m][n][0] + bv.x, c[m][n][1] + bv.y);
                        *(float2*)(g_num + r0 * DD + col) = z2;
                        *(float2*)(g_den + r0 * DD + col) = z2;
                    }
                    if (r0 + 8 < NN) {
                        *(float2*)(g_Ah + (r0 + 8) * DD + col) =
                            make_float2(c[m][n][2] + bv.x, c[m][n][3] + bv.y);
                        *(float2*)(g_num + (r0 + 8) * DD + col) = z2;
                        *(float2*)(g_den + (r0 + 8) * DD + col) = z2;
                    }
                } else {
                    if (r0 < NN)
                        *(__half2*)(outh + r0 * ostride + col) =
                            __floats2half2_rn(c[m][n][0] + bv.x, c[m][n][1] + bv.y);
                    if (r0 + 8 < NN)
                        *(__half2*)(outh + (r0 + 8) * ostride + col) =
                            __floats2half2_rn(c[m][n][2] + bv.x, c[m][n][3] + bv.y);
                }
            }
        }
        __syncthreads();   // all ldsm done before next commit overwrites A
    }
}

// ---------------- edge GEMM: f16 2-pass + fused epilogue ----------------------
__global__ void __launch_bounds__(256, 2) edge_gemm(const float* __restrict__ e,
        const float* __restrict__ b2, const int* __restrict__ src,
        const int* __restrict__ dst, const float* __restrict__ snorm_e) {
    extern __shared__ __align__(16) char sm[];
    load_W_generic(sm, (const uint32_t*)(g_Wh_hi + 2 * DD * DD),
                   (const uint32_t*)(g_Wh_lo + 2 * DD * DD));

    const uint32_t smb = smem_u32(sm);
    __half* sD = (__half*)sm;   // 64 rows x 264B, overlays A region
    const int lane = threadIdx.x & 31, w = threadIdx.x >> 5;
    const int m0 = (w & 1) * 32, n0 = (w >> 1) * 32;
    const int tig = lane & 3, gg = lane >> 2;
    const float se = snorm_e[0];
    const float4 bb = ((const float4*)b2)[lane];

    int gcur = -1;
    float4 s4 = make_float4(0, 0, 0, 0), q4 = make_float4(0, 0, 0, 0);

    float2 pf[16];
    long tile = blockIdx.x;
    if (tile < EDGE_TILES) prefetch_tile<true>(e, tile, EE, pf);
    for (; tile < EDGE_TILES; tile += gridDim.x) {
        commit_tile_f16(sm, pf);
        __syncthreads();

        // ---- prefetch this tile's gather rows into L2 (covered by MMA) ----
        {
            const long rb = tile * MT + w * 8;
            const int4 pA = *(const int4*)(src + rb);
            const int4 pB = *(const int4*)(src + rb + 4);
            const int4 qA = *(const int4*)(dst + rb);
            const int4 qB = *(const int4*)(dst + rb + 4);
            const int ps[8] = {pA.x, pA.y, pA.z, pA.w, pB.x, pB.y, pB.z, pB.w};
            const int pd[8] = {qA.x, qA.y, qA.z, qA.w, qB.x, qB.y, qB.z, qB.w};
#pragma unroll
            for (int ed = 0; ed < 8; ed++) {
                if (lane < 6) {
                    const __half* a = (lane < 4)
                        ? g_DB + (size_t)ps[ed] * 256 + lane * 64
                        : g_EhH + (size_t)pd[ed] * 128 + (lane - 4) * 64;
                    prefetchL2(a);
                }
            }
        }

        long nt = tile + gridDim.x;
        if (nt < EDGE_TILES) prefetch_tile<true>(e, nt, EE, pf);

        float c[2][4][4];
        mma_compute_f16(smb, c);
        __syncthreads();   // all ldsm of A done before sD overwrites the region

#pragma unroll
        for (int m = 0; m < 2; m++) {
            int r = m0 + m * 16 + gg;
#pragma unroll
            for (int n = 0; n < 4; n++) {
                int col = n0 + n * 8 + tig * 2;
                *(__half2*)((char*)sD + r * 264 + col * 2) =
                    __floats2half2_rn(c[m][n][0], c[m][n][1]);
                *(__half2*)((char*)sD + (r + 8) * 264 + col * 2) =
                    __floats2half2_rn(c[m][n][2], c[m][n][3]);
            }
        }
        __syncthreads();

        const long rbase = tile * MT + w * 8;
        const int4 sA = *(const int4*)(src + rbase);
        const int4 sB = *(const int4*)(src + rbase + 4);
        const int4 dA = *(const int4*)(dst + rbase);
        const int4 dB4 = *(const int4*)(dst + rbase + 4);
        const int svr[8] = {sA.x, sA.y, sA.z, sA.w, sB.x, sB.y, sB.z, sB.w};
        const int dvr[8] = {dA.x, dA.y, dA.z, dA.w, dB4.x, dB4.y, dB4.z, dB4.w};

#pragma unroll
        for (int r = 0; r < 8; r++) {
            const int row = w * 8 + r;
            const long grow = rbase + r;
            const int s = svr[r];
            const int d = dvr[r];
            uint2 cu = *(uint2*)((char*)sD + row * 264 + lane * 8);
            float2 c01 = __half22float2(*(__half2*)&cu.x);
            float2 c23 = __half22float2(*(__half2*)&cu.y);
            uint2 du = *(const uint2*)(g_DB + (size_t)s * 256 + lane * 4);
            uint2 bu = *(const uint2*)(g_DB + (size_t)s * 256 + 128 + lane * 4);
            uint2 eu = *(const uint2*)(g_EhH + (size_t)d * 128 + lane * 4);
            float2 d01 = __half22float2(*(__half2*)&du.x);
            float2 d23 = __half22float2(*(__half2*)&du.y);
            float2 b01 = __half22float2(*(__half2*)&bu.x);
            float2 b23 = __half22float2(*(__half2*)&bu.y);
            float2 e01 = __half22float2(*(__half2*)&eu.x);
            float2 e23 = __half22float2(*(__half2*)&eu.y);
            float ex = c01.x + bb.x + d01.x + e01.x;
            float ey = c01.y + bb.y + d01.y + e01.y;
            float ez = c23.x + bb.z + d23.x + e23.x;
            float ew = c23.y + bb.w + d23.y + e23.y;
            float4 eo = make_float4(ex * se, ey * se, ez * se, ew * se);
            uint2 ev;
            *(__half2*)&ev.x = __floats2half2_rn(eo.x, eo.y);
            *(__half2*)&ev.y = __floats2half2_rn(eo.z, eo.w);
            __stcs(((uint2*)(g_EW + (size_t)grow * DD)) + lane, ev);
            float sx = sigt(ex);
            float sy = sigt(ey);
            float sz = sigt(ez);
            float sv = sigt(ew);
            redv4(&g_num[d * DD + lane * 4],
                  make_float4(sx * b01.x, sy * b01.y, sz * b23.x, sv * b23.y));
            redv4(&g_den[d * DD + lane * 4], make_float4(sx, sy, sz, sv));
            const int gid = (int)(grow / GNE);
            if (gid != gcur) {
                if (gcur >= 0) {
                    redv4(&g_sum[NG * DD + gcur * DD + lane * 4], s4);
                    redv4(&g_sq[NG * DD + gcur * DD + lane * 4], q4);
                }
                gcur = gid;
                s4 = make_float4(0, 0, 0, 0);
                q4 = make_float4(0, 0, 0, 0);
            }
            s4.x += eo.x; s4.y += eo.y; s4.z += eo.z; s4.w += eo.w;
            q4.x = fmaf(eo.x, eo.x, q4.x); q4.y = fmaf(eo.y, eo.y, q4.y);
            q4.z = fmaf(eo.z, eo.z, q4.z); q4.w = fmaf(eo.w, eo.w, q4.w);
        }
        __syncthreads();   // epilogue reads of sD done before next commit
    }
    if (gcur >= 0) {
        redv4(&g_sum[NG * DD + gcur * DD + lane * 4], s4);
        redv4(&g_sq[NG * DD + gcur * DD + lane * 4], q4);
    }
}

// ---------------- fused node epilogue + h-stats (vectorized) -------------------
__global__ void node_epi_stats(const float* __restrict__ h,
                               const float* __restrict__ snorm_n,
                               float* __restrict__ outh) {
    const int g = blockIdx.y;
    const int c4 = threadIdx.x & 31;
    const int rlane = threadIdx.x >> 5;
    int per = (GNH + gridDim.x - 1) / gridDim.x;
    int r0 = blockIdx.x * per;
    int r1 = min(GNH, r0 + per);
    const float sn = snorm_n[0];
    float4 s = make_float4(0, 0, 0, 0), q = make_float4(0, 0, 0, 0);
    for (int r = r0 + rlane; r < r1; r += 8) {
        size_t i = ((size_t)g * GNH + r) * 32 + c4;
        float4 den = ((const float4*)g_den)[i];
        float4 num = ((const float4*)g_num)[i];
        float4 ah  = ((const float4*)g_Ah)[i];
        float4 hv  = ((const float4*)h)[i];
        float4 o;
        o.x = ((den.x > 0.f) ? (ah.x + num.x / (den.x + EPS_RED)) : hv.x) * sn;
        o.y = ((den.y > 0.f) ? (ah.y + num.y / (den.y + EPS_RED)) : hv.y) * sn;
        o.z = ((den.z > 0.f) ? (ah.z + num.z / (den.z + EPS_RED)) : hv.z) * sn;
        o.w = ((den.w > 0.f) ? (ah.w + num.w / (den.w + EPS_RED)) : hv.w) * sn;
        ((float4*)outh)[i] = o;
        s.x += o.x; s.y += o.y; s.z += o.z; s.w += o.w;
        q.x = fmaf(o.x, o.x, q.x); q.y = fmaf(o.y, o.y, q.y);
        q.z = fmaf(o.z, o.z, q.z); q.w = fmaf(o.w, o.w, q.w);
    }
    if (r0 < r1) {
        redv4(&g_sum[g * DD + c4 * 4], s);
        redv4(&g_sq[g * DD + c4 * 4], q);
    }
}

// inline mean/rstd from g_sum/g_sq (f4 = tid&31 is loop-invariant)
__device__ __forceinline__ void load_meanrstd(int statOff, int g, int f4, float n,
                                              float4& mn, float4& rs) {
    float4 s = *(const float4*)(g_sum + statOff + g * DD + f4 * 4);
    float4 q = *(const float4*)(g_sq + statOff + g * DD + f4 * 4);
    mn.x = s.x / n; mn.y = s.y / n; mn.z = s.z / n; mn.w = s.w / n;
    float inv = 1.f / (n - 1.f);
    rs.x = 1.f / (sqrtf(fmaxf((q.x - s.x * mn.x) * inv, 0.f)) + EPS_NORM);
    rs.y = 1.f / (sqrtf(fmaxf((q.y - s.y * mn.y) * inv, 0.f)) + EPS_NORM);
    rs.z = 1.f / (sqrtf(fmaxf((q.z - s.z * mn.z) * inv, 0.f)) + EPS_NORM);
    rs.w = 1.f / (sqrtf(fmaxf((q.w - s.w * mn.w) * inv, 0.f)) + EPS_NORM);
}

// ---------------- finalize h (f32 in-place, inline meanstd) --------------------
__global__ void finalize_h(float* __restrict__ io, const float* __restrict__ resid,
                           const float* __restrict__ gamma,
                           const float* __restrict__ beta) {
    int g = blockIdx.y;
    size_t base4 = (size_t)g * GNH * 32;
    int tot4 = GNH * 32;
    const int f4 = threadIdx.x & 31;
    float4 mn, rs;
    load_meanrstd(0, g, f4, (float)GNH, mn, rs);
    float4 ga = ((const float4*)gamma)[f4];
    float4 be = ((const float4*)beta)[f4];
    for (int i = blockIdx.x * blockDim.x + threadIdx.x; i < tot4;
         i += gridDim.x * blockDim.x) {
        float4 xv = __ldcs(((const float4*)io) + base4 + i);
        float4 rv = __ldcs(((const float4*)resid) + base4 + i);
        float4 o;
        o.x = rv.x + fmaxf(fmaf(ga.x, (xv.x - mn.x) * rs.x, be.x), 0.f);
        o.y = rv.y + fmaxf(fmaf(ga.y, (xv.y - mn.y) * rs.y, be.y), 0.f);
        o.z = rv.z + fmaxf(fmaf(ga.z, (xv.z - mn.z) * rs.z, be.z), 0.f);
        o.w = rv.w + fmaxf(fmaf(ga.w, (xv.w - mn.w) * rs.w, be.w), 0.f);
        __stcs(((float4*)io) + base4 + i, o);
    }
}

// ---------------- finalize e (f16 staging -> f32 out, inline meanstd) ----------
__global__ void finalize_e_f16(float* __restrict__ out, const float* __restrict__ resid,
                               const float* __restrict__ gamma,
                               const float* __restrict__ beta) {
    int g = blockIdx.y;
    size_t base4 = (size_t)g * GNE * 32;
    int tot4 = GNE * 32;
    const int f4 = threadIdx.x & 31;
    float4 mn, rs;
    load_meanrstd(NG * DD, g, f4, (float)GNE, mn, rs);
    float4 ga = ((const float4*)gamma)[f4];
    float4 be = ((const float4*)beta)[f4];
    for (int i = blockIdx.x * blockDim.x + threadIdx.x; i < tot4;
         i += gridDim.x * blockDim.x) {
        uint2 ev = __ldcs(((const uint2*)g_EW) + base4 + i);
        float2 x01 = __half22float2(*(__half2*)&ev.x);
        float2 x23 = __half22float2(*(__half2*)&ev.y);
        float4 rv = __ldcs(((const float4*)resid) + base4 + i);
        float4 o;
        o.x = rv.x + fmaxf(fmaf(ga.x, (x01.x - mn.x) * rs.x, be.x), 0.f);
        o.y = rv.y + fmaxf(fmaf(ga.y, (x01.y - mn.y) * rs.y, be.y), 0.f);
        o.z = rv.z + fmaxf(fmaf(ga.z, (x23.x - mn.z) * rs.z, be.z), 0.f);
        o.w = rv.w + fmaxf(fmaf(ga.w, (x23.y - mn.w) * rs.w, be.w), 0.f);
        __stcs(((float4*)out) + base4 + i, o);
    }
}

// ---------------- launcher -------------------------------------------------------
extern "C" void kernel_launch(void* const* d_in, const int* in_sizes, int n_in,
                              void* d_out, int out_size) {
    const float* h   = (const float*)d_in[0];
    const float* e   = (const float*)d_in[1];
    const int*   src = (const int*)d_in[2];
    const int*   dst = (const int*)d_in[3];
    const float* snn = (const float*)d_in[4];
    const float* sne = (const float*)d_in[5];
    const float* W   = (const float*)d_in[6];
    const float* b   = (const float*)d_in[7];
    const float* gam_h = (const float*)d_in[8];
    const float* bet_h = (const float*)d_in[9];
    const float* gam_e = (const float*)d_in[10];
    const float* bet_e = (const float*)d_in[11];

    float* out_h = (float*)d_out;
    float* out_e = out_h + (size_t)NN * DD;

    cudaFuncSetAttribute((const void*)node_gemm,
                         cudaFuncAttributeMaxDynamicSharedMemorySize, E_SMEM);
    cudaFuncSetAttribute((const void*)edge_gemm,
                         cudaFuncAttributeMaxDynamicSharedMemorySize, E_SMEM);

    splitW_kernel<<<(5 * DD * DD + 255) / 256, 256>>>(W);
    node_gemm<<<dim3(76, 4), 256, E_SMEM>>>(h, b);
    edge_gemm<<<296, 256, E_SMEM>>>(e, b + 2 * DD, src, dst, sne);

    node_epi_stats<<<dim3(40, NG), 256>>>(h, snn, out_h);
    finalize_h<<<dim3(160, NG), 256>>>(out_h, h, gam_h, bet_h);
    finalize_e_f16<<<dim3(1024, NG), 256>>>(out_e, e, gam_e, bet_e);
}

// round 15
// speedup vs baseline: 1.0177x; 1.0177x over previous
#include <cuda_runtime.h>
#include <cuda_bf16.h>
#include <cuda_fp16.h>
#include <math.h>
#include <stdint.h>

#define NN 50000
#define EE 600000
#define DD 128
#define GNH 5000
#define GNE 60000
#define NG 10
#define EPS_NORM 1e-5f
#define EPS_RED  1e-6f

#define MT 64
#define NODE_TILES ((NN + MT - 1) / MT)   // 782
#define EDGE_TILES (EE / MT)              // 9375 (exact)

// ---- GEMM smem layout (f16 2-pass) ----
#define EW_HI 17408
#define EW_LO 52224
#define N_SMEM 87040              // node kernel: A + W(hi,lo)
#define SD_OFF 87040              // edge kernel: separate sD region
#define E_SMEM 103936             // + 64 rows x 264B

// ---------------- scratch (device globals; no allocation allowed) ----------
__device__ float g_Ah[NN * DD];
__device__ __half g_DB[NN * 256];    // src-indexed f16: [node][0:128)=Dh, [128:256)=Bh
__device__ __half g_EhH[NN * DD];    // dst-indexed f16 Eh
__device__ __half g_EW[(size_t)EE * DD];  // f16 staged e_new*snorm
__device__ float g_num[NN * DD];
__device__ float g_den[NN * DD];
__device__ float g_sum[2 * NG * DD];
__device__ float g_sq[2 * NG * DD];
__device__ __half g_Wh_hi[5 * DD * DD];   // transposed [l][n][k], f16 hi
__device__ __half g_Wh_lo[5 * DD * DD];   // f16 lo (residual)

// ---------------- helpers ----------------------------------------------------
__device__ __forceinline__ uint32_t smem_u32(const void* p) {
    uint32_t a;
    asm("{ .reg .u64 t; cvta.to.shared.u64 t, %1; cvt.u32.u64 %0, t; }" : "=r"(a) : "l"(p));
    return a;
}
__device__ __forceinline__ void ldsm4(uint32_t a[4], uint32_t addr) {
    asm volatile("ldmatrix.sync.aligned.m8n8.x4.shared.b16 {%0,%1,%2,%3}, [%4];"
                 : "=r"(a[0]), "=r"(a[1]), "=r"(a[2]), "=r"(a[3]) : "r"(addr));
}
__device__ __forceinline__ void mma16816h(float c[4], const uint32_t a[4],
                                          uint32_t b0, uint32_t b1) {
    asm volatile("mma.sync.aligned.m16n8k16.row.col.f32.f16.f16.f32 "
                 "{%0,%1,%2,%3}, {%4,%5,%6,%7}, {%8,%9}, {%0,%1,%2,%3};"
                 : "+f"(c[0]), "+f"(c[1]), "+f"(c[2]), "+f"(c[3])
                 : "r"(a[0]), "r"(a[1]), "r"(a[2]), "r"(a[3]), "r"(b0), "r"(b1));
}
__device__ __forceinline__ void redv4(float* p, float4 v) {
    asm volatile("red.global.add.v4.f32 [%0], {%1,%2,%3,%4};"
                 :: "l"(p), "f"(v.x), "f"(v.y), "f"(v.z), "f"(v.w) : "memory");
}
__device__ __forceinline__ void prefetchL2(const void* p) {
    asm volatile("prefetch.global.L2 [%0];" :: "l"(p));
}
// sigmoid via single-MUFU tanh: sig(x) = 0.5*tanh(x/2) + 0.5
__device__ __forceinline__ float sigt(float x) {
    float t;
    asm("tanh.approx.f32 %0, %1;" : "=f"(t) : "f"(x * 0.5f));
    return fmaf(t, 0.5f, 0.5f);
}

// ---------------- zero scratch + W transpose/split (merged, independent) ------
__global__ void prep_kernel(const float* __restrict__ W) {
    const int tid = blockIdx.x * blockDim.x + threadIdx.x;
    // part 1: splitW (first 81920 threads, one element each)
    if (tid < 5 * DD * DD) {
        int j = tid & 16383, n = j >> 7, k = j & 127;
        int l = tid >> 14;
        float v = W[(l << 14) + (k << 7) + n];
        __half hh = __float2half_rn(v);
        g_Wh_hi[tid] = hh;
        g_Wh_lo[tid] = __float2half_rn(v - __half2float(hh));
    }
    // part 2: zero num/den/sum/sq (grid-stride)
    const int nnd = NN * DD;
    const int total = 2 * nnd + 2 * 2 * NG * DD;
    for (int i = tid; i < total; i += gridDim.x * blockDim.x) {
        if (i < nnd)           g_num[i] = 0.f;
        else if (i < 2 * nnd)  g_den[i - nnd] = 0.f;
        else {
            int j = i - 2 * nnd;
            if (j < 2 * NG * DD) g_sum[j] = 0.f;
            else                 g_sq[j - 2 * NG * DD] = 0.f;
        }
    }
}

// ---------------- W loader (once per CTA) -------------------------------------
__device__ __forceinline__ void load_W_generic(char* sm,
                                               const uint32_t* __restrict__ WH,
                                               const uint32_t* __restrict__ WL) {
    for (int u = threadIdx.x; u < 128 * 64; u += 256) {
        int r = u >> 6, kk = u & 63;
        *(uint32_t*)(sm + EW_HI + r * 272 + kk * 4) = WH[u];
        *(uint32_t*)(sm + EW_LO + r * 272 + kk * 4) = WL[u];
    }
}

// ---------------- A-tile prefetch (f32 -> regs) --------------------------------
template <bool STREAM>
__device__ __forceinline__ void prefetch_tile(const float* __restrict__ X,
                                              long tile, int M, float2 pf[16]) {
    const float2* X2 = (const float2*)X;
    const int t = threadIdx.x;
#pragma unroll
    for (int j = 0; j < 16; j++) {
        int u = t + j * 256;
        int r = u >> 6, kk = u & 63;
        long grow = tile * MT + r;
        if (grow < M) pf[j] = STREAM ? __ldcs(&X2[grow * 64 + kk]) : X2[grow * 64 + kk];
        else          pf[j] = make_float2(0.f, 0.f);
    }
}
// f16 commit (A at smem offset 0)
__device__ __forceinline__ void commit_tile_f16(char* sm, const float2 pf[16]) {
    const int t = threadIdx.x;
#pragma unroll
    for (int j = 0; j < 16; j++) {
        int u = t + j * 256;
        int r = u >> 6, kk = u & 63;
        *(__half2*)(sm + r * 272 + kk * 4) = __floats2half2_rn(pf[j].x, pf[j].y);
    }
}

// ---------------- warp-mma: f16 2-pass, 64x128 tile ----------------------------
__device__ __forceinline__ void mma_compute_f16(uint32_t smb, float c[2][4][4]) {
    const int lane = threadIdx.x & 31;
    const int w = threadIdx.x >> 5;
    const int m0 = (w & 1) * 32, n0 = (w >> 1) * 32;
#pragma unroll
    for (int m = 0; m < 2; m++)
#pragma unroll
        for (int n = 0; n < 4; n++)
#pragma unroll
            for (int i = 0; i < 4; i++) c[m][n][i] = 0.f;

    const uint32_t aBase = smb + (m0 + (lane & 15)) * 272 + (lane >> 4) * 16;
    const uint32_t bBase = smb + EW_HI +
        (n0 + (lane & 7) + ((lane >> 4) & 1) * 8) * 272 + ((lane >> 3) & 1) * 16;

#pragma unroll
    for (int k = 0; k < 8; k++) {
        uint32_t aH0[4], aH1[4];
        ldsm4(aH0, aBase + k * 32);
        ldsm4(aH1, aBase + 16 * 272 + k * 32);
#pragma unroll
        for (int np = 0; np < 2; np++) {
            uint32_t bH[4], bL[4];
            ldsm4(bH, bBase + np * 16 * 272 + k * 32);
            ldsm4(bL, bBase + (EW_LO - EW_HI) + np * 16 * 272 + k * 32);
#pragma unroll
            for (int nn = 0; nn < 2; nn++) {
                const int nc = np * 2 + nn;
                mma16816h(c[0][nc], aH0, bH[nn * 2], bH[nn * 2 + 1]);
                mma16816h(c[1][nc], aH1, bH[nn * 2], bH[nn * 2 + 1]);
                mma16816h(c[0][nc], aH0, bL[nn * 2], bL[nn * 2 + 1]);
                mma16816h(c[1][nc], aH1, bL[nn * 2], bL[nn * 2 + 1]);
            }
        }
    }
}

// ---------------- node GEMMs: persistent tiles, layer = blockIdx.y -----------
__global__ void __launch_bounds__(256, 2) node_gemm(const float* __restrict__ h,
                                                    const float* __restrict__ b) {
    extern __shared__ __align__(16) char sm[];
    const int lmap[4] = {0, 1, 3, 4};
    const int l = lmap[blockIdx.y];
    __half* outh;
    int ostride = 256;
    if (blockIdx.y == 1)      outh = g_DB + 128;
    else if (blockIdx.y == 2) outh = g_DB;
    else                      { outh = g_EhH; ostride = 128; }
    load_W_generic(sm, (const uint32_t*)(g_Wh_hi + l * DD * DD),
                   (const uint32_t*)(g_Wh_lo + l * DD * DD));

    const uint32_t smb = smem_u32(sm);
    const float* bias = b + l * DD;
    const int lane = threadIdx.x & 31, w = threadIdx.x >> 5;
    const int m0 = (w & 1) * 32, n0 = (w >> 1) * 32;
    const int tig = lane & 3, gg = lane >> 2;

    float2 pf[16];
    long tile = blockIdx.x;
    if (tile < NODE_TILES) prefetch_tile<false>(h, tile, NN, pf);
    for (; tile < NODE_TILES; tile += gridDim.x) {
        commit_tile_f16(sm, pf);
        __syncthreads();
        long nt = tile + gridDim.x;
        if (nt < NODE_TILES) prefetch_tile<false>(h, nt, NN, pf);

        float c[2][4][4];
        mma_compute_f16(smb, c);

#pragma unroll
        for (int m = 0; m < 2; m++) {
            long r0 = tile * MT + m0 + m * 16 + gg;
#pragma unroll
            for (int n = 0; n < 4; n++) {
                int col = n0 + n * 8 + tig * 2;
                float2 bv = *(const float2*)(bias + col);
                if (blockIdx.y == 0) {
                    if (r0 < NN)
                        *(float2*)(g_Ah + r0 * DD + col) =
                            make_float2(c[m][n][0] + bv.x, c[m][n][1] + bv.y);
                    if (r0 + 8 < NN)
                        *(float2*)(g_Ah + (r0 + 8) * DD + col) =
                            make_float2(c[m][n][2] + bv.x, c[m][n][3] + bv.y);
                } else {
                    if (r0 < NN)
                        *(__half2*)(outh + r0 * ostride + col) =
                            __floats2half2_rn(c[m][n][0] + bv.x, c[m][n][1] + bv.y);
                    if (r0 + 8 < NN)
                        *(__half2*)(outh + (r0 + 8) * ostride + col) =
                            __floats2half2_rn(c[m][n][2] + bv.x, c[m][n][3] + bv.y);
                }
            }
        }
        __syncthreads();   // all ldsm done before next commit overwrites A
    }
}

// ---------------- edge GEMM: f16 2-pass + fused epilogue ----------------------
// separate sD region -> only 2 __syncthreads per tile
__global__ void __launch_bounds__(256, 2) edge_gemm(const float* __restrict__ e,
        const float* __restrict__ b2, const int* __restrict__ src,
        const int* __restrict__ dst, const float* __restrict__ snorm_e) {
    extern __shared__ __align__(16) char sm[];
    load_W_generic(sm, (const uint32_t*)(g_Wh_hi + 2 * DD * DD),
                   (const uint32_t*)(g_Wh_lo + 2 * DD * DD));

    const uint32_t smb = smem_u32(sm);
    __half* sD = (__half*)(sm + SD_OFF);   // dedicated region: 64 rows x 264B
    const int lane = threadIdx.x & 31, w = threadIdx.x >> 5;
    const int m0 = (w & 1) * 32, n0 = (w >> 1) * 32;
    const int tig = lane & 3, gg = lane >> 2;
    const float se = snorm_e[0];
    const float4 bb = ((const float4*)b2)[lane];

    int gcur = -1;
    float4 s4 = make_float4(0, 0, 0, 0), q4 = make_float4(0, 0, 0, 0);

    float2 pf[16];
    long tile = blockIdx.x;
    if (tile < EDGE_TILES) prefetch_tile<true>(e, tile, EE, pf);
    for (; tile < EDGE_TILES; tile += gridDim.x) {
        commit_tile_f16(sm, pf);
        __syncthreads();   // (1) A visible; prev-iter epilogue sD reads done

        // ---- prefetch this tile's gather rows into L2 (covered by MMA) ----
        {
            const long rb = tile * MT + w * 8;
            const int4 pA = *(const int4*)(src + rb);
            const int4 pB = *(const int4*)(src + rb + 4);
            const int4 qA = *(const int4*)(dst + rb);
            const int4 qB = *(const int4*)(dst + rb + 4);
            const int ps[8] = {pA.x, pA.y, pA.z, pA.w, pB.x, pB.y, pB.z, pB.w};
            const int pd[8] = {qA.x, qA.y, qA.z, qA.w, qB.x, qB.y, qB.z, qB.w};
#pragma unroll
            for (int ed = 0; ed < 8; ed++) {
                if (lane < 6) {
                    const __half* a = (lane < 4)
                        ? g_DB + (size_t)ps[ed] * 256 + lane * 64
                        : g_EhH + (size_t)pd[ed] * 128 + (lane - 4) * 64;
                    prefetchL2(a);
                }
            }
        }

        long nt = tile + gridDim.x;
        if (nt < EDGE_TILES) prefetch_tile<true>(e, nt, EE, pf);

        float c[2][4][4];
        mma_compute_f16(smb, c);

        // stage accumulators to dedicated sD (no WAR vs A region)
#pragma unroll
        for (int m = 0; m < 2; m++) {
            int r = m0 + m * 16 + gg;
#pragma unroll
            for (int n = 0; n < 4; n++) {
                int col = n0 + n * 8 + tig * 2;
                *(__half2*)((char*)sD + r * 264 + col * 2) =
                    __floats2half2_rn(c[m][n][0], c[m][n][1]);
                *(__half2*)((char*)sD + (r + 8) * 264 + col * 2) =
                    __floats2half2_rn(c[m][n][2], c[m][n][3]);
            }
        }
        __syncthreads();   // (2) sD visible to epilogue

        const long rbase = tile * MT + w * 8;
        const int4 sA = *(const int4*)(src + rbase);
        const int4 sB = *(const int4*)(src + rbase + 4);
        const int4 dA = *(const int4*)(dst + rbase);
        const int4 dB4 = *(const int4*)(dst + rbase + 4);
        const int svr[8] = {sA.x, sA.y, sA.z, sA.w, sB.x, sB.y, sB.z, sB.w};
        const int dvr[8] = {dA.x, dA.y, dA.z, dA.w, dB4.x, dB4.y, dB4.z, dB4.w};

#pragma unroll
        for (int r = 0; r < 8; r++) {
            const int row = w * 8 + r;
            const long grow = rbase + r;
            const int s = svr[r];
            const int d = dvr[r];
            uint2 cu = *(uint2*)((char*)sD + row * 264 + lane * 8);
            float2 c01 = __half22float2(*(__half2*)&cu.x);
            float2 c23 = __half22float2(*(__half2*)&cu.y);
            uint2 du = *(const uint2*)(g_DB + (size_t)s * 256 + lane * 4);
            uint2 bu = *(const uint2*)(g_DB + (size_t)s * 256 + 128 + lane * 4);
            uint2 eu = *(const uint2*)(g_EhH + (size_t)d * 128 + lane * 4);
            float2 d01 = __half22float2(*(__half2*)&du.x);
            float2 d23 = __half22float2(*(__half2*)&du.y);
            float2 b01 = __half22float2(*(__half2*)&bu.x);
            float2 b23 = __half22float2(*(__half2*)&bu.y);
            float2 e01 = __half22float2(*(__half2*)&eu.x);
            float2 e23 = __half22float2(*(__half2*)&eu.y);
            float ex = c01.x + bb.x + d01.x + e01.x;
            float ey = c01.y + bb.y + d01.y + e01.y;
            float ez = c23.x + bb.z + d23.x + e23.x;
            float ew = c23.y + bb.w + d23.y + e23.y;
            float4 eo = make_float4(ex * se, ey * se, ez * se, ew * se);
            uint2 ev;
            *(__half2*)&ev.x = __floats2half2_rn(eo.x, eo.y);
            *(__half2*)&ev.y = __floats2half2_rn(eo.z, eo.w);
            __stcs(((uint2*)(g_EW + (size_t)grow * DD)) + lane, ev);
            float sx = sigt(ex);
            float sy = sigt(ey);
            float sz = sigt(ez);
            float sv = sigt(ew);
            redv4(&g_num[d * DD + lane * 4],
                  make_float4(sx * b01.x, sy * b01.y, sz * b23.x, sv * b23.y));
            redv4(&g_den[d * DD + lane * 4], make_float4(sx, sy, sz, sv));
            const int gid = (int)(grow / GNE);
            if (gid != gcur) {
                if (gcur >= 0) {
                    redv4(&g_sum[NG * DD + gcur * DD + lane * 4], s4);
                    redv4(&g_sq[NG * DD + gcur * DD + lane * 4], q4);
                }
                gcur = gid;
                s4 = make_float4(0, 0, 0, 0);
                q4 = make_float4(0, 0, 0, 0);
            }
            s4.x += eo.x; s4.y += eo.y; s4.z += eo.z; s4.w += eo.w;
            q4.x = fmaf(eo.x, eo.x, q4.x); q4.y = fmaf(eo.y, eo.y, q4.y);
            q4.z = fmaf(eo.z, eo.z, q4.z); q4.w = fmaf(eo.w, eo.w, q4.w);
        }
        // no sync here: next iter's sync (1) orders epilogue sD reads vs sD writes
    }
    if (gcur >= 0) {
        redv4(&g_sum[NG * DD + gcur * DD + lane * 4], s4);
        redv4(&g_sq[NG * DD + gcur * DD + lane * 4], q4);
    }
}

// ---------------- fused node epilogue + h-stats (vectorized) -------------------
__global__ void node_epi_stats(const float* __restrict__ h,
                               const float* __restrict__ snorm_n,
                               float* __restrict__ outh) {
    const int g = blockIdx.y;
    const int c4 = threadIdx.x & 31;
    const int rlane = threadIdx.x >> 5;
    int per = (GNH + gridDim.x - 1) / gridDim.x;
    int r0 = blockIdx.x * per;
    int r1 = min(GNH, r0 + per);
    const float sn = snorm_n[0];
    float4 s = make_float4(0, 0, 0, 0), q = make_float4(0, 0, 0, 0);
    for (int r = r0 + rlane; r < r1; r += 8) {
        size_t i = ((size_t)g * GNH + r) * 32 + c4;
        float4 den = ((const float4*)g_den)[i];
        float4 num = ((const float4*)g_num)[i];
        float4 ah  = ((const float4*)g_Ah)[i];
        float4 hv  = ((const float4*)h)[i];
        float4 o;
        o.x = ((den.x > 0.f) ? (ah.x + num.x / (den.x + EPS_RED)) : hv.x) * sn;
        o.y = ((den.y > 0.f) ? (ah.y + num.y / (den.y + EPS_RED)) : hv.y) * sn;
        o.z = ((den.z > 0.f) ? (ah.z + num.z / (den.z + EPS_RED)) : hv.z) * sn;
        o.w = ((den.w > 0.f) ? (ah.w + num.w / (den.w + EPS_RED)) : hv.w) * sn;
        ((float4*)outh)[i] = o;
        s.x += o.x; s.y += o.y; s.z += o.z; s.w += o.w;
        q.x = fmaf(o.x, o.x, q.x); q.y = fmaf(o.y, o.y, q.y);
        q.z = fmaf(o.z, o.z, q.z); q.w = fmaf(o.w, o.w, q.w);
    }
    if (r0 < r1) {
        redv4(&g_sum[g * DD + c4 * 4], s);
        redv4(&g_sq[g * DD + c4 * 4], q);
    }
}

// inline mean/rstd from g_sum/g_sq (f4 = tid&31 is loop-invariant)
__device__ __forceinline__ void load_meanrstd(int statOff, int g, int f4, float n,
                                              float4& mn, float4& rs) {
    float4 s = *(const float4*)(g_sum + statOff + g * DD + f4 * 4);
    float4 q = *(const float4*)(g_sq + statOff + g * DD + f4 * 4);
    mn.x = s.x / n; mn.y = s.y / n; mn.z = s.z / n; mn.w = s.w / n;
    float inv = 1.f / (n - 1.f);
    rs.x = 1.f / (sqrtf(fmaxf((q.x - s.x * mn.x) * inv, 0.f)) + EPS_NORM);
    rs.y = 1.f / (sqrtf(fmaxf((q.y - s.y * mn.y) * inv, 0.f)) + EPS_NORM);
    rs.z = 1.f / (sqrtf(fmaxf((q.z - s.z * mn.z) * inv, 0.f)) + EPS_NORM);
    rs.w = 1.f / (sqrtf(fmaxf((q.w - s.w * mn.w) * inv, 0.f)) + EPS_NORM);
}

// ---------------- finalize h (f32 in-place, inline meanstd) --------------------
__global__ void finalize_h(float* __restrict__ io, const float* __restrict__ resid,
                           const float* __restrict__ gamma,
                           const float* __restrict__ beta) {
    int g = blockIdx.y;
    size_t base4 = (size_t)g * GNH * 32;
    int tot4 = GNH * 32;
    const int f4 = threadIdx.x & 31;
    float4 mn, rs;
    load_meanrstd(0, g, f4, (float)GNH, mn, rs);
    float4 ga = ((const float4*)gamma)[f4];
    float4 be = ((const float4*)beta)[f4];
    for (int i = blockIdx.x * blockDim.x + threadIdx.x; i < tot4;
         i += gridDim.x * blockDim.x) {
        float4 xv = __ldcs(((const float4*)io) + base4 + i);
        float4 rv = __ldcs(((const float4*)resid) + base4 + i);
        float4 o;
        o.x = rv.x + fmaxf(fmaf(ga.x, (xv.x - mn.x) * rs.x, be.x), 0.f);
        o.y = rv.y + fmaxf(fmaf(ga.y, (xv.y - mn.y) * rs.y, be.y), 0.f);
        o.z = rv.z + fmaxf(fmaf(ga.z, (xv.z - mn.z) * rs.z, be.z), 0.f);
        o.w = rv.w + fmaxf(fmaf(ga.w, (xv.w - mn.w) * rs.w, be.w), 0.f);
        __stcs(((float4*)io) + base4 + i, o);
    }
}

// ---------------- finalize e (f16 staging -> f32 out, inline meanstd) ----------
__global__ void finalize_e_f16(float* __restrict__ out, const float* __restrict__ resid,
                               const float* __restrict__ gamma,
                               const float* __restrict__ beta) {
    int g = blockIdx.y;
    size_t base4 = (size_t)g * GNE * 32;
    int tot4 = GNE * 32;
    const int f4 = threadIdx.x & 31;
    float4 mn, rs;
    load_meanrstd(NG * DD, g, f4, (float)GNE, mn, rs);
    float4 ga = ((const float4*)gamma)[f4];
    float4 be = ((const float4*)beta)[f4];
    for (int i = blockIdx.x * blockDim.x + threadIdx.x; i < tot4;
         i += gridDim.x * blockDim.x) {
        uint2 ev = __ldcs(((const uint2*)g_EW) + base4 + i);
        float2 x01 = __half22float2(*(__half2*)&ev.x);
        float2 x23 = __half22float2(*(__half2*)&ev.y);
        float4 rv = __ldcs(((const float4*)resid) + base4 + i);
        float4 o;
        o.x = rv.x + fmaxf(fmaf(ga.x, (x01.x - mn.x) * rs.x, be.x), 0.f);
        o.y = rv.y + fmaxf(fmaf(ga.y, (x01.y - mn.y) * rs.y, be.y), 0.f);
        o.z = rv.z + fmaxf(fmaf(ga.z, (x23.x - mn.z) * rs.z, be.z), 0.f);
        o.w = rv.w + fmaxf(fmaf(ga.w, (x23.y - mn.w) * rs.w, be.w), 0.f);
        __stcs(((float4*)out) + base4 + i, o);
    }
}

// ---------------- launcher -------------------------------------------------------
extern "C" void kernel_launch(void* const* d_in, const int* in_sizes, int n_in,
                              void* d_out, int out_size) {
    const float* h   = (const float*)d_in[0];
    const float* e   = (const float*)d_in[1];
    const int*   src = (const int*)d_in[2];
    const int*   dst = (const int*)d_in[3];
    const float* snn = (const float*)d_in[4];
    const float* sne = (const float*)d_in[5];
    const float* W   = (const float*)d_in[6];
    const float* b   = (const float*)d_in[7];
    const float* gam_h = (const float*)d_in[8];
    const float* bet_h = (const float*)d_in[9];
    const float* gam_e = (const float*)d_in[10];
    const float* bet_e = (const float*)d_in[11];

    float* out_h = (float*)d_out;
    float* out_e = out_h + (size_t)NN * DD;

    cudaFuncSetAttribute((const void*)node_gemm,
                         cudaFuncAttributeMaxDynamicSharedMemorySize, N_SMEM);
    cudaFuncSetAttribute((const void*)edge_gemm,
                         cudaFuncAttributeMaxDynamicSharedMemorySize, E_SMEM);

    prep_kernel<<<1024, 256>>>(W);

    node_gemm<<<dim3(74, 4), 256, N_SMEM>>>(h, b);
    edge_gemm<<<296, 256, E_SMEM>>>(e, b + 2 * DD, src, dst, sne);

    node_epi_stats<<<dim3(40, NG), 256>>>(h, snn, out_h);
    finalize_h<<<dim3(160, NG), 256>>>(out_h, h, gam_h, bet_h);
    finalize_e_f16<<<dim3(1024, NG), 256>>>(out_e, e, gam_e, bet_e);
}

// round 16
// speedup vs baseline: 1.0989x; 1.0799x over previous
#include <cuda_runtime.h>
#include <cuda_bf16.h>
#include <cuda_fp16.h>
#include <math.h>
#include <stdint.h>

#define NN 50000
#define EE 600000
#define DD 128
#define GNH 5000
#define GNE 60000
#define NG 10
#define EPS_NORM 1e-5f
#define EPS_RED  1e-6f

#define MT 64
#define NODE_TILES ((NN + MT - 1) / MT)   // 782
#define EDGE_TILES (EE / MT)              // 9375 (exact)

// ---- GEMM smem layout (f16 single-pass) ----
// A: [0, 17408) 64 rows x 272B; W: [17408, 52224) 128 rows x 272B
#define EW_HI 17408
#define N_SMEM 52224              // node kernel: A + W
#define SD_OFF 52224              // edge kernel: sD region
#define E_SMEM 69120              // + 64 rows x 264B

// ---------------- scratch (device globals; no allocation allowed) ----------
__device__ float g_Ah[NN * DD];
__device__ __half g_DB[NN * 256];    // src-indexed f16: [node][0:128)=Dh, [128:256)=Bh
__device__ __half g_EhH[NN * DD];    // dst-indexed f16 Eh
__device__ __half g_EW[(size_t)EE * DD];  // f16 staged e_new*snorm
__device__ float g_num[NN * DD];
__device__ float g_den[NN * DD];
__device__ float g_sum[2 * NG * DD];
__device__ float g_sq[2 * NG * DD];
__device__ __half g_Wh[5 * DD * DD];   // transposed [l][n][k], f16

// ---------------- helpers ----------------------------------------------------
__device__ __forceinline__ uint32_t smem_u32(const void* p) {
    uint32_t a;
    asm("{ .reg .u64 t; cvta.to.shared.u64 t, %1; cvt.u32.u64 %0, t; }" : "=r"(a) : "l"(p));
    return a;
}
__device__ __forceinline__ void ldsm4(uint32_t a[4], uint32_t addr) {
    asm volatile("ldmatrix.sync.aligned.m8n8.x4.shared.b16 {%0,%1,%2,%3}, [%4];"
                 : "=r"(a[0]), "=r"(a[1]), "=r"(a[2]), "=r"(a[3]) : "r"(addr));
}
__device__ __forceinline__ void mma16816h(float c[4], const uint32_t a[4],
                                          uint32_t b0, uint32_t b1) {
    asm volatile("mma.sync.aligned.m16n8k16.row.col.f32.f16.f16.f32 "
                 "{%0,%1,%2,%3}, {%4,%5,%6,%7}, {%8,%9}, {%0,%1,%2,%3};"
                 : "+f"(c[0]), "+f"(c[1]), "+f"(c[2]), "+f"(c[3])
                 : "r"(a[0]), "r"(a[1]), "r"(a[2]), "r"(a[3]), "r"(b0), "r"(b1));
}
__device__ __forceinline__ void redv4(float* p, float4 v) {
    asm volatile("red.global.add.v4.f32 [%0], {%1,%2,%3,%4};"
                 :: "l"(p), "f"(v.x), "f"(v.y), "f"(v.z), "f"(v.w) : "memory");
}
__device__ __forceinline__ void prefetchL2(const void* p) {
    asm volatile("prefetch.global.L2 [%0];" :: "l"(p));
}
// sigmoid via single-MUFU tanh: sig(x) = 0.5*tanh(x/2) + 0.5
__device__ __forceinline__ float sigt(float x) {
    float t;
    asm("tanh.approx.f32 %0, %1;" : "=f"(t) : "f"(x * 0.5f));
    return fmaf(t, 0.5f, 0.5f);
}

// ---------------- zero scratch + W transpose/split (merged, independent) ------
__global__ void prep_kernel(const float* __restrict__ W) {
    const int tid = blockIdx.x * blockDim.x + threadIdx.x;
    if (tid < 5 * DD * DD) {
        int j = tid & 16383, n = j >> 7, k = j & 127;
        int l = tid >> 14;
        g_Wh[tid] = __float2half_rn(W[(l << 14) + (k << 7) + n]);
    }
    const int nnd = NN * DD;
    const int total = 2 * nnd + 2 * 2 * NG * DD;
    for (int i = tid; i < total; i += gridDim.x * blockDim.x) {
        if (i < nnd)           g_num[i] = 0.f;
        else if (i < 2 * nnd)  g_den[i - nnd] = 0.f;
        else {
            int j = i - 2 * nnd;
            if (j < 2 * NG * DD) g_sum[j] = 0.f;
            else                 g_sq[j - 2 * NG * DD] = 0.f;
        }
    }
}

// ---------------- W loader (once per CTA) -------------------------------------
__device__ __forceinline__ void load_W_generic(char* sm,
                                               const uint32_t* __restrict__ WH) {
    for (int u = threadIdx.x; u < 128 * 64; u += 256) {
        int r = u >> 6, kk = u & 63;
        *(uint32_t*)(sm + EW_HI + r * 272 + kk * 4) = WH[u];
    }
}

// ---------------- A-tile prefetch (f32 -> regs) --------------------------------
template <bool STREAM>
__device__ __forceinline__ void prefetch_tile(const float* __restrict__ X,
                                              long tile, int M, float2 pf[16]) {
    const float2* X2 = (const float2*)X;
    const int t = threadIdx.x;
#pragma unroll
    for (int j = 0; j < 16; j++) {
        int u = t + j * 256;
        int r = u >> 6, kk = u & 63;
        long grow = tile * MT + r;
        if (grow < M) pf[j] = STREAM ? __ldcs(&X2[grow * 64 + kk]) : X2[grow * 64 + kk];
        else          pf[j] = make_float2(0.f, 0.f);
    }
}
// f16 commit (A at smem offset 0)
__device__ __forceinline__ void commit_tile_f16(char* sm, const float2 pf[16]) {
    const int t = threadIdx.x;
#pragma unroll
    for (int j = 0; j < 16; j++) {
        int u = t + j * 256;
        int r = u >> 6, kk = u & 63;
        *(__half2*)(sm + r * 272 + kk * 4) = __floats2half2_rn(pf[j].x, pf[j].y);
    }
}

// ---------------- warp-mma: f16 single-pass, 64x128 tile -----------------------
__device__ __forceinline__ void mma_compute_f16(uint32_t smb, float c[2][4][4]) {
    const int lane = threadIdx.x & 31;
    const int w = threadIdx.x >> 5;
    const int m0 = (w & 1) * 32, n0 = (w >> 1) * 32;
#pragma unroll
    for (int m = 0; m < 2; m++)
#pragma unroll
        for (int n = 0; n < 4; n++)
#pragma unroll
            for (int i = 0; i < 4; i++) c[m][n][i] = 0.f;

    const uint32_t aBase = smb + (m0 + (lane & 15)) * 272 + (lane >> 4) * 16;
    const uint32_t bBase = smb + EW_HI +
        (n0 + (lane & 7) + ((lane >> 4) & 1) * 8) * 272 + ((lane >> 3) & 1) * 16;

#pragma unroll
    for (int k = 0; k < 8; k++) {
        uint32_t aH0[4], aH1[4];
        ldsm4(aH0, aBase + k * 32);
        ldsm4(aH1, aBase + 16 * 272 + k * 32);
#pragma unroll
        for (int np = 0; np < 2; np++) {
            uint32_t bH[4];
            ldsm4(bH, bBase + np * 16 * 272 + k * 32);
#pragma unroll
            for (int nn = 0; nn < 2; nn++) {
                const int nc = np * 2 + nn;
                mma16816h(c[0][nc], aH0, bH[nn * 2], bH[nn * 2 + 1]);
                mma16816h(c[1][nc], aH1, bH[nn * 2], bH[nn * 2 + 1]);
            }
        }
    }
}

// ---------------- node GEMMs: persistent tiles, layer = blockIdx.y -----------
__global__ void __launch_bounds__(256, 2) node_gemm(const float* __restrict__ h,
                                                    const float* __restrict__ b) {
    extern __shared__ __align__(16) char sm[];
    const int lmap[4] = {0, 1, 3, 4};
    const int l = lmap[blockIdx.y];
    __half* outh;
    int ostride = 256;
    if (blockIdx.y == 1)      outh = g_DB + 128;
    else if (blockIdx.y == 2) outh = g_DB;
    else                      { outh = g_EhH; ostride = 128; }
    load_W_generic(sm, (const uint32_t*)(g_Wh + l * DD * DD));

    const uint32_t smb = smem_u32(sm);
    const float* bias = b + l * DD;
    const int lane = threadIdx.x & 31, w = threadIdx.x >> 5;
    const int m0 = (w & 1) * 32, n0 = (w >> 1) * 32;
    const int tig = lane & 3, gg = lane >> 2;

    float2 pf[16];
    long tile = blockIdx.x;
    if (tile < NODE_TILES) prefetch_tile<false>(h, tile, NN, pf);
    for (; tile < NODE_TILES; tile += gridDim.x) {
        commit_tile_f16(sm, pf);
        __syncthreads();
        long nt = tile + gridDim.x;
        if (nt < NODE_TILES) prefetch_tile<false>(h, nt, NN, pf);

        float c[2][4][4];
        mma_compute_f16(smb, c);

#pragma unroll
        for (int m = 0; m < 2; m++) {
            long r0 = tile * MT + m0 + m * 16 + gg;
#pragma unroll
            for (int n = 0; n < 4; n++) {
                int col = n0 + n * 8 + tig * 2;
                float2 bv = *(const float2*)(bias + col);
                if (blockIdx.y == 0) {
                    if (r0 < NN)
                        *(float2*)(g_Ah + r0 * DD + col) =
                            make_float2(c[m][n][0] + bv.x, c[m][n][1] + bv.y);
                    if (r0 + 8 < NN)
                        *(float2*)(g_Ah + (r0 + 8) * DD + col) =
                            make_float2(c[m][n][2] + bv.x, c[m][n][3] + bv.y);
                } else {
                    if (r0 < NN)
                        *(__half2*)(outh + r0 * ostride + col) =
                            __floats2half2_rn(c[m][n][0] + bv.x, c[m][n][1] + bv.y);
                    if (r0 + 8 < NN)
                        *(__half2*)(outh + (r0 + 8) * ostride + col) =
                            __floats2half2_rn(c[m][n][2] + bv.x, c[m][n][3] + bv.y);
                }
            }
        }
        __syncthreads();   // all ldsm done before next commit overwrites A
    }
}

// ---------------- edge GEMM: f16 single-pass + fused epilogue ------------------
__global__ void __launch_bounds__(256, 2) edge_gemm(const float* __restrict__ e,
        const float* __restrict__ b2, const int* __restrict__ src,
        const int* __restrict__ dst, const float* __restrict__ snorm_e) {
    extern __shared__ __align__(16) char sm[];
    load_W_generic(sm, (const uint32_t*)(g_Wh + 2 * DD * DD));

    const uint32_t smb = smem_u32(sm);
    __half* sD = (__half*)(sm + SD_OFF);   // dedicated region: 64 rows x 264B
    const int lane = threadIdx.x & 31, w = threadIdx.x >> 5;
    const int m0 = (w & 1) * 32, n0 = (w >> 1) * 32;
    const int tig = lane & 3, gg = lane >> 2;
    const float se = snorm_e[0];
    const float4 bb = ((const float4*)b2)[lane];

    int gcur = -1;
    float4 s4 = make_float4(0, 0, 0, 0), q4 = make_float4(0, 0, 0, 0);

    float2 pf[16];
    long tile = blockIdx.x;
    if (tile < EDGE_TILES) prefetch_tile<true>(e, tile, EE, pf);
    for (; tile < EDGE_TILES; tile += gridDim.x) {
        commit_tile_f16(sm, pf);
        __syncthreads();   // (1) A visible; prev-iter epilogue sD reads done

        // ---- prefetch this tile's gather rows into L2 (covered by MMA) ----
        {
            const long rb = tile * MT + w * 8;
            const int4 pA = *(const int4*)(src + rb);
            const int4 pB = *(const int4*)(src + rb + 4);
            const int4 qA = *(const int4*)(dst + rb);
            const int4 qB = *(const int4*)(dst + rb + 4);
            const int ps[8] = {pA.x, pA.y, pA.z, pA.w, pB.x, pB.y, pB.z, pB.w};
            const int pd[8] = {qA.x, qA.y, qA.z, qA.w, qB.x, qB.y, qB.z, qB.w};
#pragma unroll
            for (int ed = 0; ed < 8; ed++) {
                if (lane < 6) {
                    const __half* a = (lane < 4)
                        ? g_DB + (size_t)ps[ed] * 256 + lane * 64
                        : g_EhH + (size_t)pd[ed] * 128 + (lane - 4) * 64;
                    prefetchL2(a);
                }
            }
        }

        long nt = tile + gridDim.x;
        if (nt < EDGE_TILES) prefetch_tile<true>(e, nt, EE, pf);

        float c[2][4][4];
        mma_compute_f16(smb, c);

        // stage accumulators to dedicated sD (no WAR vs A region)
#pragma unroll
        for (int m = 0; m < 2; m++) {
            int r = m0 + m * 16 + gg;
#pragma unroll
            for (int n = 0; n < 4; n++) {
                int col = n0 + n * 8 + tig * 2;
                *(__half2*)((char*)sD + r * 264 + col * 2) =
                    __floats2half2_rn(c[m][n][0], c[m][n][1]);
                *(__half2*)((char*)sD + (r + 8) * 264 + col * 2) =
                    __floats2half2_rn(c[m][n][2], c[m][n][3]);
            }
        }
        __syncthreads();   // (2) sD visible to epilogue

        const long rbase = tile * MT + w * 8;
        const int4 sA = *(const int4*)(src + rbase);
        const int4 sB = *(const int4*)(src + rbase + 4);
        const int4 dA = *(const int4*)(dst + rbase);
        const int4 dB4 = *(const int4*)(dst + rbase + 4);
        const int svr[8] = {sA.x, sA.y, sA.z, sA.w, sB.x, sB.y, sB.z, sB.w};
        const int dvr[8] = {dA.x, dA.y, dA.z, dA.w, dB4.x, dB4.y, dB4.z, dB4.w};

#pragma unroll
        for (int r = 0; r < 8; r++) {
            const int row = w * 8 + r;
            const long grow = rbase + r;
            const int s = svr[r];
            const int d = dvr[r];
            uint2 cu = *(uint2*)((char*)sD + row * 264 + lane * 8);
            float2 c01 = __half22float2(*(__half2*)&cu.x);
            float2 c23 = __half22float2(*(__half2*)&cu.y);
            uint2 du = *(const uint2*)(g_DB + (size_t)s * 256 + lane * 4);
            uint2 bu = *(const uint2*)(g_DB + (size_t)s * 256 + 128 + lane * 4);
            uint2 eu = *(const uint2*)(g_EhH + (size_t)d * 128 + lane * 4);
            float2 d01 = __half22float2(*(__half2*)&du.x);
            float2 d23 = __half22float2(*(__half2*)&du.y);
            float2 b01 = __half22float2(*(__half2*)&bu.x);
            float2 b23 = __half22float2(*(__half2*)&bu.y);
            float2 e01 = __half22float2(*(__half2*)&eu.x);
            float2 e23 = __half22float2(*(__half2*)&eu.y);
            float ex = c01.x + bb.x + d01.x + e01.x;
            float ey = c01.y + bb.y + d01.y + e01.y;
            float ez = c23.x + bb.z + d23.x + e23.x;
            float ew = c23.y + bb.w + d23.y + e23.y;
            float4 eo = make_float4(ex * se, ey * se, ez * se, ew * se);
            uint2 ev;
            *(__half2*)&ev.x = __floats2half2_rn(eo.x, eo.y);
            *(__half2*)&ev.y = __floats2half2_rn(eo.z, eo.w);
            __stcs(((uint2*)(g_EW + (size_t)grow * DD)) + lane, ev);
            float sx = sigt(ex);
            float sy = sigt(ey);
            float sz = sigt(ez);
            float sv = sigt(ew);
            redv4(&g_num[d * DD + lane * 4],
                  make_float4(sx * b01.x, sy * b01.y, sz * b23.x, sv * b23.y));
            redv4(&g_den[d * DD + lane * 4], make_float4(sx, sy, sz, sv));
            const int gid = (int)(grow / GNE);
            if (gid != gcur) {
                if (gcur >= 0) {
                    redv4(&g_sum[NG * DD + gcur * DD + lane * 4], s4);
                    redv4(&g_sq[NG * DD + gcur * DD + lane * 4], q4);
                }
                gcur = gid;
                s4 = make_float4(0, 0, 0, 0);
                q4 = make_float4(0, 0, 0, 0);
            }
            s4.x += eo.x; s4.y += eo.y; s4.z += eo.z; s4.w += eo.w;
            q4.x = fmaf(eo.x, eo.x, q4.x); q4.y = fmaf(eo.y, eo.y, q4.y);
            q4.z = fmaf(eo.z, eo.z, q4.z); q4.w = fmaf(eo.w, eo.w, q4.w);
        }
        // no sync: next iter's sync (1) orders epilogue sD reads vs sD writes
    }
    if (gcur >= 0) {
        redv4(&g_sum[NG * DD + gcur * DD + lane * 4], s4);
        redv4(&g_sq[NG * DD + gcur * DD + lane * 4], q4);
    }
}

// ---------------- fused node epilogue + h-stats (vectorized) -------------------
__global__ void node_epi_stats(const float* __restrict__ h,
                               const float* __restrict__ snorm_n,
                               float* __restrict__ outh) {
    const int g = blockIdx.y;
    const int c4 = threadIdx.x & 31;
    const int rlane = threadIdx.x >> 5;
    int per = (GNH + gridDim.x - 1) / gridDim.x;
    int r0 = blockIdx.x * per;
    int r1 = min(GNH, r0 + per);
    const float sn = snorm_n[0];
    float4 s = make_float4(0, 0, 0, 0), q = make_float4(0, 0, 0, 0);
    for (int r = r0 + rlane; r < r1; r += 8) {
        size_t i = ((size_t)g * GNH + r) * 32 + c4;
        float4 den = ((const float4*)g_den)[i];
        float4 num = ((const float4*)g_num)[i];
        float4 ah  = ((const float4*)g_Ah)[i];
        float4 hv  = ((const float4*)h)[i];
        float4 o;
        o.x = ((den.x > 0.f) ? (ah.x + num.x / (den.x + EPS_RED)) : hv.x) * sn;
        o.y = ((den.y > 0.f) ? (ah.y + num.y / (den.y + EPS_RED)) : hv.y) * sn;
        o.z = ((den.z > 0.f) ? (ah.z + num.z / (den.z + EPS_RED)) : hv.z) * sn;
        o.w = ((den.w > 0.f) ? (ah.w + num.w / (den.w + EPS_RED)) : hv.w) * sn;
        ((float4*)outh)[i] = o;
        s.x += o.x; s.y += o.y; s.z += o.z; s.w += o.w;
        q.x = fmaf(o.x, o.x, q.x); q.y = fmaf(o.y, o.y, q.y);
        q.z = fmaf(o.z, o.z, q.z); q.w = fmaf(o.w, o.w, q.w);
    }
    if (r0 < r1) {
        redv4(&g_sum[g * DD + c4 * 4], s);
        redv4(&g_sq[g * DD + c4 * 4], q);
    }
}

// inline mean/rstd from g_sum/g_sq (f4 = tid&31 is loop-invariant)
__device__ __forceinline__ void load_meanrstd(int statOff, int g, int f4, float n,
                                              float4& mn, float4& rs) {
    float4 s = *(const float4*)(g_sum + statOff + g * DD + f4 * 4);
    float4 q = *(const float4*)(g_sq + statOff + g * DD + f4 * 4);
    mn.x = s.x / n; mn.y = s.y / n; mn.z = s.z / n; mn.w = s.w / n;
    float inv = 1.f / (n - 1.f);
    rs.x = 1.f / (sqrtf(fmaxf((q.x - s.x * mn.x) * inv, 0.f)) + EPS_NORM);
    rs.y = 1.f / (sqrtf(fmaxf((q.y - s.y * mn.y) * inv, 0.f)) + EPS_NORM);
    rs.z = 1.f / (sqrtf(fmaxf((q.z - s.z * mn.z) * inv, 0.f)) + EPS_NORM);
    rs.w = 1.f / (sqrtf(fmaxf((q.w - s.w * mn.w) * inv, 0.f)) + EPS_NORM);
}

// ---------------- finalize h (f32 in-place, inline meanstd) --------------------
__global__ void finalize_h(float* __restrict__ io, const float* __restrict__ resid,
                           const float* __restrict__ gamma,
                           const float* __restrict__ beta) {
    int g = blockIdx.y;
    size_t base4 = (size_t)g * GNH * 32;
    int tot4 = GNH * 32;
    const int f4 = threadIdx.x & 31;
    float4 mn, rs;
    load_meanrstd(0, g, f4, (float)GNH, mn, rs);
    float4 ga = ((const float4*)gamma)[f4];
    float4 be = ((const float4*)beta)[f4];
    for (int i = blockIdx.x * blockDim.x + threadIdx.x; i < tot4;
         i += gridDim.x * blockDim.x) {
        float4 xv = __ldcs(((const float4*)io) + base4 + i);
        float4 rv = __ldcs(((const float4*)resid) + base4 + i);
        float4 o;
        o.x = rv.x + fmaxf(fmaf(ga.x, (xv.x - mn.x) * rs.x, be.x), 0.f);
        o.y = rv.y + fmaxf(fmaf(ga.y, (xv.y - mn.y) * rs.y, be.y), 0.f);
        o.z = rv.z + fmaxf(fmaf(ga.z, (xv.z - mn.z) * rs.z, be.z), 0.f);
        o.w = rv.w + fmaxf(fmaf(ga.w, (xv.w - mn.w) * rs.w, be.w), 0.f);
        __stcs(((float4*)io) + base4 + i, o);
    }
}

// ---------------- finalize e (f16 staging -> f32 out, inline meanstd) ----------
__global__ void finalize_e_f16(float* __restrict__ out, const float* __restrict__ resid,
                               const float* __restrict__ gamma,
                               const float* __restrict__ beta) {
    int g = blockIdx.y;
    size_t base4 = (size_t)g * GNE * 32;
    int tot4 = GNE * 32;
    const int f4 = threadIdx.x & 31;
    float4 mn, rs;
    load_meanrstd(NG * DD, g, f4, (float)GNE, mn, rs);
    float4 ga = ((const float4*)gamma)[f4];
    float4 be = ((const float4*)beta)[f4];
    for (int i = blockIdx.x * blockDim.x + threadIdx.x; i < tot4;
         i += gridDim.x * blockDim.x) {
        uint2 ev = __ldcs(((const uint2*)g_EW) + base4 + i);
        float2 x01 = __half22float2(*(__half2*)&ev.x);
        float2 x23 = __half22float2(*(__half2*)&ev.y);
        float4 rv = __ldcs(((const float4*)resid) + base4 + i);
        float4 o;
        o.x = rv.x + fmaxf(fmaf(ga.x, (x01.x - mn.x) * rs.x, be.x), 0.f);
        o.y = rv.y + fmaxf(fmaf(ga.y, (x01.y - mn.y) * rs.y, be.y), 0.f);
        o.z = rv.z + fmaxf(fmaf(ga.z, (x23.x - mn.z) * rs.z, be.z), 0.f);
        o.w = rv.w + fmaxf(fmaf(ga.w, (x23.y - mn.w) * rs.w, be.w), 0.f);
        __stcs(((float4*)out) + base4 + i, o);
    }
}

// ---------------- launcher -------------------------------------------------------
extern "C" void kernel_launch(void* const* d_in, const int* in_sizes, int n_in,
                              void* d_out, int out_size) {
    const float* h   = (const float*)d_in[0];
    const float* e   = (const float*)d_in[1];
    const int*   src = (const int*)d_in[2];
    const int*   dst = (const int*)d_in[3];
    const float* snn = (const float*)d_in[4];
    const float* sne = (const float*)d_in[5];
    const float* W   = (const float*)d_in[6];
    const float* b   = (const float*)d_in[7];
    const float* gam_h = (const float*)d_in[8];
    const float* bet_h = (const float*)d_in[9];
    const float* gam_e = (const float*)d_in[10];
    const float* bet_e = (const float*)d_in[11];

    float* out_h = (float*)d_out;
    float* out_e = out_h + (size_t)NN * DD;

    cudaFuncSetAttribute((const void*)node_gemm,
                         cudaFuncAttributeMaxDynamicSharedMemorySize, N_SMEM);
    cudaFuncSetAttribute((const void*)edge_gemm,
                         cudaFuncAttributeMaxDynamicSharedMemorySize, E_SMEM);

    prep_kernel<<<1024, 256>>>(W);

    node_gemm<<<dim3(74, 4), 256, N_SMEM>>>(h, b);
    edge_gemm<<<296, 256, E_SMEM>>>(e, b + 2 * DD, src, dst, sne);

    node_epi_stats<<<dim3(40, NG), 256>>>(h, snn, out_h);
    finalize_h<<<dim3(160, NG), 256>>>(out_h, h, gam_h, bet_h);
    finalize_e_f16<<<dim3(1024, NG), 256>>>(out_e, e, gam_e, bet_e);
}